// round 1
// baseline (speedup 1.0000x reference)
#include <cuda_runtime.h>
#include <cuda_fp16.h>
#include <cstdint>

#define H 8
#define B 4
#define S 2048
#define D 8
#define F 64
#define HB 32            // H*B
#define TILES 16
#define ROWS_CTA 128     // S / TILES
#define WARPS 4
#define RPW (ROWS_CTA / WARPS)   // 32 rows per warp
#define RBLK 4                   // rows in flight per lane

// Scratch (static __device__, no allocation)
__device__ float g_q [HB * S * D];   // [hb][s][d], pre-scaled by log2e/sqrt(8)
__device__ float g_kT[HB * D * S];   // [hb][d][s]
__device__ float g_vT[HB * D * S];   // [hb][d][s]
__device__ float g_part[HB * TILES * D];  // per-CTA head colsum partials

__device__ __forceinline__ float ex2f(float x) {
    float y; asm("ex2.approx.ftz.f32 %0, %1;" : "=f"(y) : "f"(x)); return y;
}

// ---------------------------------------------------------------------------
// Kernel 1: QKV projection. block = 192 threads handles 8 (b,s) rows.
// thread t -> tensor = t/64 (q,k,v), c = t%64 -> (h = c/8, d = c%8).
// q is written [hb][s][d] scaled by log2e/sqrt(8); k,v written transposed [hb][d][s].
// ---------------------------------------------------------------------------
__global__ void __launch_bounds__(192) qkv_kernel(
    const float* __restrict__ x,
    const float* __restrict__ Wq,
    const float* __restrict__ Wk,
    const float* __restrict__ Wv)
{
    __shared__ float xs[8 * 64];
    const int tid = threadIdx.x;
    const int rowbase = blockIdx.x * 8;

    for (int i = tid; i < 512; i += 192)
        xs[i] = x[(size_t)rowbase * 64 + i];
    __syncthreads();

    const int tensor = tid / 64;
    const int c = tid % 64;
    const int h = c >> 3, d = c & 7;
    const float* W = (tensor == 0) ? Wq : ((tensor == 1) ? Wk : Wv);

    float acc[8];
#pragma unroll
    for (int r = 0; r < 8; ++r) acc[r] = 0.f;

#pragma unroll
    for (int f4 = 0; f4 < 16; ++f4) {
        const float w0 = W[(h * 64 + f4 * 4 + 0) * 8 + d];
        const float w1 = W[(h * 64 + f4 * 4 + 1) * 8 + d];
        const float w2 = W[(h * 64 + f4 * 4 + 2) * 8 + d];
        const float w3 = W[(h * 64 + f4 * 4 + 3) * 8 + d];
#pragma unroll
        for (int r = 0; r < 8; ++r) {
            float4 xv = *(const float4*)&xs[r * 64 + f4 * 4];  // warp broadcast
            acc[r] = fmaf(xv.x, w0, fmaf(xv.y, w1, fmaf(xv.z, w2, fmaf(xv.w, w3, acc[r]))));
        }
    }

    const float QS = 0.51006975f;  // log2(e) / sqrt(8)
#pragma unroll
    for (int r = 0; r < 8; ++r) {
        const int row = rowbase + r;
        const int b = row >> 11;
        const int s = row & 2047;
        const int hb = h * 4 + b;
        if (tensor == 0)      g_q [((size_t)hb * S + s) * 8 + d] = acc[r] * QS;
        else if (tensor == 1) g_kT[((size_t)hb * 8 + d) * S + s] = acc[r];
        else                  g_vT[((size_t)hb * 8 + d) * S + s] = acc[r];
    }
}

// ---------------------------------------------------------------------------
// Kernel 2: attention. grid (TILES, HB), 128 threads.
// smem: kT[8][2048] (64KB) + vT[8][2048] (64KB) + q[128][8] (4KB)
//       + e-buffer fp16 [4 warps][4 rows][2048] (64KB) + reduce buf (128B)
// Each warp processes RBLK=4 rows at a time; each lane owns cols (c*128+lane*4).
// Single pass: scores -> exp2 -> row sum + head accumulation, e stashed in fp16;
// then normalized weights streamed to gmem as coalesced float4.
// ---------------------------------------------------------------------------
__global__ void __launch_bounds__(128, 1) attn_kernel(float* __restrict__ wout)
{
    extern __shared__ float sm[];
    float*  kS   = sm;                       // 16384 floats
    float*  vS   = sm + 16384;               // 16384 floats
    float*  qS   = sm + 32768;               // 1024 floats
    __half* eS   = (__half*)(sm + 33792);    // 32768 halfs (= 16384 floats)
    float*  redS = sm + 33792 + 16384;       // 32 floats

    const int tid  = threadIdx.x;
    const int lane = tid & 31;
    const int wrp  = tid >> 5;
    const int tile = blockIdx.x;
    const int hb   = blockIdx.y;

    // cooperative loads (coalesced float4)
    {
        const float4* k4 = (const float4*)(g_kT + (size_t)hb * D * S);
        const float4* v4 = (const float4*)(g_vT + (size_t)hb * D * S);
        float4* kd = (float4*)kS;
        float4* vd = (float4*)vS;
        for (int i = tid; i < (D * S) / 4; i += 128) { kd[i] = k4[i]; vd[i] = v4[i]; }
        const float4* q4 = (const float4*)(g_q + ((size_t)hb * S + tile * ROWS_CTA) * D);
        float4* qd = (float4*)qS;
        for (int i = tid; i < (ROWS_CTA * D) / 4; i += 128) qd[i] = q4[i];
    }
    __syncthreads();

    float runA[8];
#pragma unroll
    for (int d = 0; d < 8; ++d) runA[d] = 0.f;

    __half* eb = eS + (size_t)wrp * (RBLK * S);

    for (int g = 0; g < RPW / RBLK; ++g) {
        const int rl = wrp * RPW + g * RBLK;

        float qr[RBLK][8];
#pragma unroll
        for (int r = 0; r < RBLK; ++r)
#pragma unroll
            for (int d = 0; d < 8; ++d) qr[r][d] = qS[(rl + r) * 8 + d];

        float acc[RBLK][8];
        float ls[RBLK];
#pragma unroll
        for (int r = 0; r < RBLK; ++r) {
            ls[r] = 0.f;
#pragma unroll
            for (int d = 0; d < 8; ++d) acc[r][d] = 0.f;
        }

#pragma unroll 1
        for (int c = 0; c < 16; ++c) {
            const int col = c * 128 + lane * 4;

            float kk[32];
#pragma unroll
            for (int d = 0; d < 8; ++d) {
                float4 t = *(const float4*)(kS + d * S + col);
                kk[4 * d + 0] = t.x; kk[4 * d + 1] = t.y;
                kk[4 * d + 2] = t.z; kk[4 * d + 3] = t.w;
            }

            float ev[RBLK][4];
#pragma unroll
            for (int r = 0; r < RBLK; ++r) {
#pragma unroll
                for (int j = 0; j < 4; ++j) {
                    float s = qr[r][0] * kk[j];
#pragma unroll
                    for (int d = 1; d < 8; ++d) s = fmaf(qr[r][d], kk[4 * d + j], s);
                    ev[r][j] = ex2f(s);
                }
                ls[r] += (ev[r][0] + ev[r][1]) + (ev[r][2] + ev[r][3]);
            }

            // reuse kk regs for v
#pragma unroll
            for (int d = 0; d < 8; ++d) {
                float4 t = *(const float4*)(vS + d * S + col);
                kk[4 * d + 0] = t.x; kk[4 * d + 1] = t.y;
                kk[4 * d + 2] = t.z; kk[4 * d + 3] = t.w;
            }
#pragma unroll
            for (int r = 0; r < RBLK; ++r)
#pragma unroll
                for (int d = 0; d < 8; ++d) {
                    float a = acc[r][d];
                    a = fmaf(ev[r][0], kk[4 * d + 0], a);
                    a = fmaf(ev[r][1], kk[4 * d + 1], a);
                    a = fmaf(ev[r][2], kk[4 * d + 2], a);
                    a = fmaf(ev[r][3], kk[4 * d + 3], a);
                    acc[r][d] = a;
                }

#pragma unroll
            for (int r = 0; r < RBLK; ++r) {
                __half2 h01 = __floats2half2_rn(ev[r][0], ev[r][1]);
                __half2 h23 = __floats2half2_rn(ev[r][2], ev[r][3]);
                __half2* p = (__half2*)(eb + r * S + col);
                p[0] = h01; p[1] = h23;
            }
        }

        // full-row softmax denominators
#pragma unroll
        for (int r = 0; r < RBLK; ++r) {
            float v = ls[r];
#pragma unroll
            for (int o = 16; o > 0; o >>= 1) v += __shfl_xor_sync(0xffffffffu, v, o);
            ls[r] = v;
        }
        float inv[RBLK];
#pragma unroll
        for (int r = 0; r < RBLK; ++r) inv[r] = 1.0f / ls[r];

#pragma unroll
        for (int r = 0; r < RBLK; ++r)
#pragma unroll
            for (int d = 0; d < 8; ++d) runA[d] = fmaf(acc[r][d], inv[r], runA[d]);

        // stream normalized weights to gmem (coalesced float4)
        const size_t wb = ((size_t)hb * S + tile * ROWS_CTA + rl) * S;
#pragma unroll
        for (int r = 0; r < RBLK; ++r) {
            const float iv = inv[r];
            float* wr = wout + wb + (size_t)r * S;
            const __half* er = eb + r * S;
#pragma unroll 1
            for (int c = 0; c < 16; ++c) {
                const int col = c * 128 + lane * 4;
                __half2 a  = *(const __half2*)(er + col);
                __half2 b2 = *(const __half2*)(er + col + 2);
                float2 fa = __half22float2(a);
                float2 fb = __half22float2(b2);
                float4 o = make_float4(fa.x * iv, fa.y * iv, fb.x * iv, fb.y * iv);
                *(float4*)(wr + col) = o;
            }
        }
    }

    // deterministic head-colsum partial: lane reduce -> smem -> gmem
#pragma unroll
    for (int d = 0; d < 8; ++d) {
        float v = runA[d];
#pragma unroll
        for (int o = 16; o > 0; o >>= 1) v += __shfl_xor_sync(0xffffffffu, v, o);
        runA[d] = v;
    }
    if (lane == 0) {
#pragma unroll
        for (int d = 0; d < 8; ++d) redS[wrp * 8 + d] = runA[d];
    }
    __syncthreads();
    if (tid < 8) {
        float s = redS[tid] + redS[8 + tid] + redS[16 + tid] + redS[24 + tid];
        g_part[((size_t)hb * TILES + tile) * 8 + tid] = s;
    }
}

// ---------------------------------------------------------------------------
// Kernel 3: out1[b][f] = sum_{h,d} hsum[b][h*8+d] * Wo[h*8+d][f]
// ---------------------------------------------------------------------------
__global__ void __launch_bounds__(256) out_kernel(
    const float* __restrict__ Wo, float* __restrict__ out)
{
    __shared__ float hs[256];
    const int t = threadIdx.x;
    {
        const int b = t >> 6, j = t & 63;
        const int h = j >> 3, d = j & 7;
        const int hb = h * 4 + b;
        float s = 0.f;
#pragma unroll
        for (int tl = 0; tl < TILES; ++tl)
            s += g_part[((size_t)hb * TILES + tl) * 8 + d];
        hs[t] = s;
    }
    __syncthreads();
    const int b = t >> 6, f = t & 63;
    float a = 0.f;
#pragma unroll
    for (int j = 0; j < 64; ++j)
        a = fmaf(hs[b * 64 + j], Wo[j * 64 + f], a);
    out[b * 64 + f] = a;
}

// ---------------------------------------------------------------------------
extern "C" void kernel_launch(void* const* d_in, const int* in_sizes, int n_in,
                              void* d_out, int out_size)
{
    const float* x  = (const float*)d_in[0];
    const float* Wq = (const float*)d_in[1];
    const float* Wk = (const float*)d_in[2];
    const float* Wv = (const float*)d_in[3];
    const float* Wo = (const float*)d_in[4];
    float* out = (float*)d_out;

    const long long WELEMS = (long long)HB * S * S;  // 134217728
    float* wout = out;
    bool has_sum = false;
    if ((long long)out_size >= WELEMS + 256) {  // [sum(256) | weights]
        wout = out + 256;
        has_sum = true;
    }

    const int smem_bytes = (33792 + 16384 + 32) * 4;  // 200832
    cudaFuncSetAttribute(attn_kernel, cudaFuncAttributeMaxDynamicSharedMemorySize, smem_bytes);

    qkv_kernel<<<(B * S) / 8, 192>>>(x, Wq, Wk, Wv);
    attn_kernel<<<dim3(TILES, HB), 128, smem_bytes>>>(wout);
    if (has_sum) out_kernel<<<1, 256>>>(Wo, out);
}

// round 2
// speedup vs baseline: 1.0214x; 1.0214x over previous
#include <cuda_runtime.h>
#include <cuda_fp16.h>
#include <cstdint>

#define H 8
#define B 4
#define S 2048
#define D 8
#define F 64
#define HB 32            // H*B
#define TILES 16
#define ROWS_CTA 128     // S / TILES
#define WARPS 4
#define RPW (ROWS_CTA / WARPS)   // 32 rows per warp
#define RBLK 4                   // rows in flight per lane

typedef unsigned long long u64;

// Scratch (static __device__, no allocation). All tensors [hb][d][s].
__device__ float g_q [HB * D * S];   // pre-scaled by log2e/sqrt(8)
__device__ float g_kT[HB * D * S];
__device__ float g_vT[HB * D * S];
__device__ float g_part[HB * TILES * D];  // per-CTA head colsum partials

__device__ __forceinline__ float ex2f(float x) {
    float y; asm("ex2.approx.ftz.f32 %0, %1;" : "=f"(y) : "f"(x)); return y;
}
__device__ __forceinline__ u64 fma2(u64 a, u64 b, u64 c) {
    u64 d; asm("fma.rn.f32x2 %0, %1, %2, %3;" : "=l"(d) : "l"(a), "l"(b), "l"(c)); return d;
}
__device__ __forceinline__ u64 mul2u(u64 a, u64 b) {
    u64 d; asm("mul.rn.f32x2 %0, %1, %2;" : "=l"(d) : "l"(a), "l"(b)); return d;
}
__device__ __forceinline__ u64 add2u(u64 a, u64 b) {
    u64 d; asm("add.rn.f32x2 %0, %1, %2;" : "=l"(d) : "l"(a), "l"(b)); return d;
}
__device__ __forceinline__ u64 pack2(float lo, float hi) {
    u64 d; asm("mov.b64 %0, {%1, %2};" : "=l"(d) : "f"(lo), "f"(hi)); return d;
}
__device__ __forceinline__ float2 unpk2(u64 a) {
    float2 r; asm("mov.b64 {%0, %1}, %2;" : "=f"(r.x), "=f"(r.y) : "l"(a)); return r;
}

// ---------------------------------------------------------------------------
// Kernel 1: QKV projection. 256 blocks x 192 threads; 32 (b,s) rows per block.
// W staged in padded smem (conflict-free). Outputs written as contiguous
// float4 runs along s, layout [hb][d][s]. q pre-scaled by log2e/sqrt(8).
// ---------------------------------------------------------------------------
#define K1_ROWS 32
#define WPAD 520          // 512 + 8 pad floats per head -> conflict-free
__global__ void __launch_bounds__(192) qkv_kernel(
    const float* __restrict__ x,
    const float* __restrict__ Wq,
    const float* __restrict__ Wk,
    const float* __restrict__ Wv)
{
    extern __shared__ float k1sm[];
    float* xs = k1sm;                  // 32*64 = 2048 floats
    float* Ws = k1sm + 2048;           // 3 * 8 * 520 = 12480 floats

    const int tid = threadIdx.x;
    const int rowbase = blockIdx.x * K1_ROWS;

    for (int i = tid; i < K1_ROWS * 64; i += 192)
        xs[i] = x[(size_t)rowbase * 64 + i];
    const float* Wsrc[3] = {Wq, Wk, Wv};
#pragma unroll
    for (int t3 = 0; t3 < 3; ++t3) {
        const float* W = Wsrc[t3];
        for (int i = tid; i < 4096; i += 192) {
            const int h = i >> 9, rem = i & 511;
            Ws[t3 * (8 * WPAD) + h * WPAD + rem] = W[i];
        }
    }
    __syncthreads();

    const int tensor = tid / 64;
    const int c = tid % 64;
    const int h = c >> 3, d = c & 7;
    const float* Wc = Ws + tensor * (8 * WPAD) + h * WPAD;

    float acc[K1_ROWS];
#pragma unroll
    for (int r = 0; r < K1_ROWS; ++r) acc[r] = 0.f;

#pragma unroll
    for (int f4 = 0; f4 < 16; ++f4) {
        const float w0 = Wc[(f4 * 4 + 0) * 8 + d];
        const float w1 = Wc[(f4 * 4 + 1) * 8 + d];
        const float w2 = Wc[(f4 * 4 + 2) * 8 + d];
        const float w3 = Wc[(f4 * 4 + 3) * 8 + d];
#pragma unroll
        for (int r = 0; r < K1_ROWS; ++r) {
            float4 xv = *(const float4*)&xs[r * 64 + f4 * 4];  // broadcast
            acc[r] = fmaf(xv.x, w0, fmaf(xv.y, w1, fmaf(xv.z, w2, fmaf(xv.w, w3, acc[r]))));
        }
    }

    const int b = rowbase >> 11;            // constant within block
    const int s0 = rowbase & 2047;
    const int hb = h * 4 + b;
    const float QS = 0.51006975f;           // log2(e)/sqrt(8)
    float* dst;
    if (tensor == 0) {
        dst = g_q + ((size_t)hb * 8 + d) * S + s0;
#pragma unroll
        for (int i = 0; i < K1_ROWS / 4; ++i) {
            float4 v = make_float4(acc[4*i]*QS, acc[4*i+1]*QS, acc[4*i+2]*QS, acc[4*i+3]*QS);
            *(float4*)(dst + 4 * i) = v;
        }
    } else {
        dst = (tensor == 1 ? g_kT : g_vT) + ((size_t)hb * 8 + d) * S + s0;
#pragma unroll
        for (int i = 0; i < K1_ROWS / 4; ++i) {
            float4 v = make_float4(acc[4*i], acc[4*i+1], acc[4*i+2], acc[4*i+3]);
            *(float4*)(dst + 4 * i) = v;
        }
    }
}

// ---------------------------------------------------------------------------
// Kernel 2: attention. grid (TILES, HB), 128 threads, occ 1 (200KB smem).
// All heavy math as fma.rn.f32x2: scores packed over column pairs (k/v smem
// pairs are free packed operands via double2 loads; q packed {q,q} once per
// group). exp computed once; unnormalized e stashed fp16 in smem; weights
// streamed to gmem with __stcs (write-once data, evict-first).
// ---------------------------------------------------------------------------
__global__ void __launch_bounds__(128, 1) attn_kernel(float* __restrict__ wout)
{
    extern __shared__ float sm[];
    float*  kS   = sm;                       // 16384 floats
    float*  vS   = sm + 16384;               // 16384 floats
    float*  qS   = sm + 32768;               // 1024 floats [d][128]
    __half* eS   = (__half*)(sm + 33792);    // 32768 halfs
    float*  redS = sm + 33792 + 16384;       // 32 floats

    const int tid  = threadIdx.x;
    const int lane = tid & 31;
    const int wrp  = tid >> 5;
    const int tile = blockIdx.x;
    const int hb   = blockIdx.y;

    {
        const float4* k4 = (const float4*)(g_kT + (size_t)hb * D * S);
        const float4* v4 = (const float4*)(g_vT + (size_t)hb * D * S);
        float4* kd = (float4*)kS;
        float4* vd = (float4*)vS;
        for (int i = tid; i < (D * S) / 4; i += 128) { kd[i] = k4[i]; vd[i] = v4[i]; }
        // q tile: [d][128]
        for (int i = tid; i < ROWS_CTA * D; i += 128) {
            const int d = i >> 7, sl = i & 127;
            qS[i] = g_q[((size_t)hb * 8 + d) * S + tile * ROWS_CTA + sl];
        }
    }
    __syncthreads();

    float runA[8];
#pragma unroll
    for (int d = 0; d < 8; ++d) runA[d] = 0.f;

    __half* eb = eS + (size_t)wrp * (RBLK * S);

    for (int g = 0; g < RPW / RBLK; ++g) {
        const int rl = wrp * RPW + g * RBLK;

        u64 q2[RBLK][8];
#pragma unroll
        for (int r = 0; r < RBLK; ++r)
#pragma unroll
            for (int d = 0; d < 8; ++d) {
                float q = qS[d * ROWS_CTA + rl + r];
                q2[r][d] = pack2(q, q);
            }

        u64 acc2[RBLK][8];
        u64 ls2[RBLK];
        const u64 zz = 0ull;
#pragma unroll
        for (int r = 0; r < RBLK; ++r) {
            ls2[r] = zz;
#pragma unroll
            for (int d = 0; d < 8; ++d) acc2[r][d] = zz;
        }

#pragma unroll 1
        for (int c = 0; c < 16; ++c) {
            const int col = c * 128 + lane * 4;

            // k column pairs: double2 load = 2 packed f32x2 operands, free
            u64 k2[8][2];
#pragma unroll
            for (int d = 0; d < 8; ++d) {
                ulonglong2 t = *(const ulonglong2*)(kS + d * S + col);
                k2[d][0] = t.x; k2[d][1] = t.y;
            }

            u64 e2[RBLK][2];
#pragma unroll
            for (int r = 0; r < RBLK; ++r) {
                __half2 hv[2];
#pragma unroll
                for (int p = 0; p < 2; ++p) {
                    u64 s2 = mul2u(q2[r][0], k2[0][p]);
#pragma unroll
                    for (int d = 1; d < 8; ++d) s2 = fma2(q2[r][d], k2[d][p], s2);
                    float2 sv = unpk2(s2);
                    float elo = ex2f(sv.x), ehi = ex2f(sv.y);
                    e2[r][p] = pack2(elo, ehi);
                    ls2[r] = add2u(ls2[r], e2[r][p]);
                    hv[p] = __floats2half2_rn(elo, ehi);
                }
                uint2 st2;
                st2.x = *(unsigned*)&hv[0];
                st2.y = *(unsigned*)&hv[1];
                *(uint2*)(eb + r * S + col) = st2;
            }

            // v column pairs
            u64 v2[8][2];
#pragma unroll
            for (int d = 0; d < 8; ++d) {
                ulonglong2 t = *(const ulonglong2*)(vS + d * S + col);
                v2[d][0] = t.x; v2[d][1] = t.y;
            }
#pragma unroll
            for (int r = 0; r < RBLK; ++r)
#pragma unroll
                for (int d = 0; d < 8; ++d) {
                    u64 a = acc2[r][d];
                    a = fma2(e2[r][0], v2[d][0], a);
                    a = fma2(e2[r][1], v2[d][1], a);
                    acc2[r][d] = a;
                }
        }

        // full-row softmax denominators
        float inv[RBLK];
#pragma unroll
        for (int r = 0; r < RBLK; ++r) {
            float2 lv = unpk2(ls2[r]);
            float v = lv.x + lv.y;
#pragma unroll
            for (int o = 16; o > 0; o >>= 1) v += __shfl_xor_sync(0xffffffffu, v, o);
            inv[r] = 1.0f / v;
        }

#pragma unroll
        for (int r = 0; r < RBLK; ++r)
#pragma unroll
            for (int d = 0; d < 8; ++d) {
                float2 a = unpk2(acc2[r][d]);
                runA[d] = fmaf(a.x + a.y, inv[r], runA[d]);
            }

        // stream normalized weights to gmem (coalesced float4, evict-first)
        const size_t wb = ((size_t)hb * S + tile * ROWS_CTA + rl) * S;
#pragma unroll
        for (int r = 0; r < RBLK; ++r) {
            const float iv = inv[r];
            float* wr = wout + wb + (size_t)r * S;
            const __half* er = eb + r * S;
#pragma unroll 1
            for (int c = 0; c < 16; ++c) {
                const int col = c * 128 + lane * 4;
                uint2 raw = *(const uint2*)(er + col);
                __half2 a  = *(__half2*)&raw.x;
                __half2 b2 = *(__half2*)&raw.y;
                float2 fa = __half22float2(a);
                float2 fb = __half22float2(b2);
                float4 o = make_float4(fa.x * iv, fa.y * iv, fb.x * iv, fb.y * iv);
                __stcs((float4*)(wr + col), o);
            }
        }
    }

    // deterministic head-colsum partial
#pragma unroll
    for (int d = 0; d < 8; ++d) {
        float v = runA[d];
#pragma unroll
        for (int o = 16; o > 0; o >>= 1) v += __shfl_xor_sync(0xffffffffu, v, o);
        runA[d] = v;
    }
    if (lane == 0) {
#pragma unroll
        for (int d = 0; d < 8; ++d) redS[wrp * 8 + d] = runA[d];
    }
    __syncthreads();
    if (tid < 8) {
        float s = redS[tid] + redS[8 + tid] + redS[16 + tid] + redS[24 + tid];
        g_part[((size_t)hb * TILES + tile) * 8 + tid] = s;
    }
}

// ---------------------------------------------------------------------------
// Kernel 3: out1[b][f] = sum_{h,d} hsum[b][h*8+d] * Wo[h*8+d][f]
// ---------------------------------------------------------------------------
__global__ void __launch_bounds__(256) out_kernel(
    const float* __restrict__ Wo, float* __restrict__ out)
{
    __shared__ float hs[256];
    const int t = threadIdx.x;
    {
        const int b = t >> 6, j = t & 63;
        const int h = j >> 3, d = j & 7;
        const int hb = h * 4 + b;
        float s = 0.f;
#pragma unroll
        for (int tl = 0; tl < TILES; ++tl)
            s += g_part[((size_t)hb * TILES + tl) * 8 + d];
        hs[t] = s;
    }
    __syncthreads();
    const int b = t >> 6, f = t & 63;
    float a = 0.f;
#pragma unroll
    for (int j = 0; j < 64; ++j)
        a = fmaf(hs[b * 64 + j], Wo[j * 64 + f], a);
    out[b * 64 + f] = a;
}

// ---------------------------------------------------------------------------
extern "C" void kernel_launch(void* const* d_in, const int* in_sizes, int n_in,
                              void* d_out, int out_size)
{
    const float* x  = (const float*)d_in[0];
    const float* Wq = (const float*)d_in[1];
    const float* Wk = (const float*)d_in[2];
    const float* Wv = (const float*)d_in[3];
    const float* Wo = (const float*)d_in[4];
    float* out = (float*)d_out;

    const long long WELEMS = (long long)HB * S * S;  // 134217728
    float* wout = out;
    bool has_sum = false;
    if ((long long)out_size >= WELEMS + 256) {  // [sum(256) | weights]
        wout = out + 256;
        has_sum = true;
    }

    const int k1_smem = (2048 + 3 * 8 * WPAD) * 4;        // 58112
    const int k2_smem = (33792 + 16384 + 32) * 4;         // 200832
    cudaFuncSetAttribute(qkv_kernel,  cudaFuncAttributeMaxDynamicSharedMemorySize, k1_smem);
    cudaFuncSetAttribute(attn_kernel, cudaFuncAttributeMaxDynamicSharedMemorySize, k2_smem);

    qkv_kernel<<<(B * S) / K1_ROWS, 192, k1_smem>>>(x, Wq, Wk, Wv);
    attn_kernel<<<dim3(TILES, HB), 128, k2_smem>>>(wout);
    if (has_sum) out_kernel<<<1, 256>>>(Wo, out);
}